// round 1
// baseline (speedup 1.0000x reference)
#include <cuda_runtime.h>
#include <math.h>

// ---------------- problem constants ----------------
#define NTOK   65536     // FRAMES * P * P
#define CDIM   512
#define NWIN   512
#define LWIN   128
#define NHEAD  8
#define HDIM   64

// ---------------- scratch (device globals: allocation-free) ----------------
__device__ float g_q[(size_t)NTOK * CDIM];
__device__ float g_k[(size_t)NTOK * CDIM];
__device__ float g_v[(size_t)NTOK * CDIM];
__device__ float g_o[(size_t)NTOK * CDIM];

// windowed row index m = w*128 + l  ->  natural token index n
// w = (f1*8 + h1)*8 + w1 ; l = (t*8 + ih)*8 + iw
// n = (f1*2+t)*4096 + (h1*8+ih)*64 + (w1*8+iw)
__device__ __forceinline__ int win_to_src(int m) {
    int w = m >> 7, l = m & 127;
    int w1 = w & 7, h1 = (w >> 3) & 7, f1 = w >> 6;
    int iw = l & 7, ih = (l >> 3) & 7, t  = l >> 6;
    int f = f1 * 2 + t;
    int p = h1 * 8 + ih;
    int q = w1 * 8 + iw;
    return (f << 12) + (p << 6) + q;
}

// ---------------- GEMM tiling ----------------
#define BM 128
#define BN 128
#define BK 16
#define SPAD 4           // smem row pad (floats)
#define LDA (BM + SPAD)  // 132

// =====================================================================
// Kernel 1: QKV projection, gathered A rows (window partition fused).
//   Out[m, c] = sum_k x[n(m), k] * W[c, k]
// grid: (12, 512)  -> blockIdx.x: wsel(3) x ntile(4); blockIdx.y: mtile
// =====================================================================
__global__ __launch_bounds__(256, 2)
void qkv_gemm(const float* __restrict__ x,
              const float* __restrict__ Wq,
              const float* __restrict__ Wk,
              const float* __restrict__ Wv)
{
    __shared__ float As[BK][LDA];
    __shared__ float Bs[BK][LDA];

    const int tid   = threadIdx.x;
    const int mtile = blockIdx.y;
    const int bx    = blockIdx.x;
    const int wsel  = bx >> 2;
    const int ntile = bx & 3;

    const float* W   = (wsel == 0) ? Wq : (wsel == 1) ? Wk : Wv;
    float*       Out = (wsel == 0) ? g_q : (wsel == 1) ? g_k : g_v;

    // loader mapping: idx = tid + i*256 ; row = idx>>2 ; kq = tid&3
    const int kq   = tid & 3;
    const int row0 = tid >> 2;          // 0..63
    const int row1 = row0 + 64;         // 64..127

    const int n0 = win_to_src(mtile * BM + row0);
    const int n1 = win_to_src(mtile * BM + row1);
    const float* aptr0 = x + (size_t)n0 * CDIM + kq * 4;
    const float* aptr1 = x + (size_t)n1 * CDIM + kq * 4;
    const float* bptr0 = W + (size_t)(ntile * BN + row0) * CDIM + kq * 4;
    const float* bptr1 = W + (size_t)(ntile * BN + row1) * CDIM + kq * 4;

    const int ty = tid >> 4;   // 0..15
    const int tx = tid & 15;   // 0..15

    float acc[8][8];
#pragma unroll
    for (int r = 0; r < 8; r++)
#pragma unroll
        for (int c = 0; c < 8; c++) acc[r][c] = 0.f;

    for (int k0 = 0; k0 < CDIM; k0 += BK) {
        float4 a0 = *(const float4*)(aptr0 + k0);
        float4 a1 = *(const float4*)(aptr1 + k0);
        float4 b0 = *(const float4*)(bptr0 + k0);
        float4 b1 = *(const float4*)(bptr1 + k0);
        const int kc = kq * 4;
        As[kc + 0][row0] = a0.x; As[kc + 1][row0] = a0.y;
        As[kc + 2][row0] = a0.z; As[kc + 3][row0] = a0.w;
        As[kc + 0][row1] = a1.x; As[kc + 1][row1] = a1.y;
        As[kc + 2][row1] = a1.z; As[kc + 3][row1] = a1.w;
        Bs[kc + 0][row0] = b0.x; Bs[kc + 1][row0] = b0.y;
        Bs[kc + 2][row0] = b0.z; Bs[kc + 3][row0] = b0.w;
        Bs[kc + 0][row1] = b1.x; Bs[kc + 1][row1] = b1.y;
        Bs[kc + 2][row1] = b1.z; Bs[kc + 3][row1] = b1.w;
        __syncthreads();

#pragma unroll
        for (int k = 0; k < BK; k++) {
            float a[8], b[8];
            *(float4*)(a)     = *(const float4*)&As[k][ty * 8];
            *(float4*)(a + 4) = *(const float4*)&As[k][ty * 8 + 4];
            *(float4*)(b)     = *(const float4*)&Bs[k][tx * 8];
            *(float4*)(b + 4) = *(const float4*)&Bs[k][tx * 8 + 4];
#pragma unroll
            for (int r = 0; r < 8; r++)
#pragma unroll
                for (int c = 0; c < 8; c++) acc[r][c] += a[r] * b[c];
        }
        __syncthreads();
    }

#pragma unroll
    for (int r = 0; r < 8; r++) {
        const int m = mtile * BM + ty * 8 + r;
        float* op = Out + (size_t)m * CDIM + ntile * BN + tx * 8;
        *(float4*)(op)     = make_float4(acc[r][0], acc[r][1], acc[r][2], acc[r][3]);
        *(float4*)(op + 4) = make_float4(acc[r][4], acc[r][5], acc[r][6], acc[r][7]);
    }
}

// =====================================================================
// Kernel 3: output projection + bias, scattered C rows (window merge fused).
//   y[n(m), c] = sum_k g_o[m, k] * Wo[c, k] + bo[c]
// grid: (4, 512)
// =====================================================================
__global__ __launch_bounds__(256, 2)
void proj_gemm(const float* __restrict__ Wo,
               const float* __restrict__ bo,
               float* __restrict__ y)
{
    __shared__ float As[BK][LDA];
    __shared__ float Bs[BK][LDA];

    const int tid   = threadIdx.x;
    const int mtile = blockIdx.y;
    const int ntile = blockIdx.x;

    const int kq   = tid & 3;
    const int row0 = tid >> 2;
    const int row1 = row0 + 64;

    const float* aptr0 = g_o + (size_t)(mtile * BM + row0) * CDIM + kq * 4;
    const float* aptr1 = g_o + (size_t)(mtile * BM + row1) * CDIM + kq * 4;
    const float* bptr0 = Wo + (size_t)(ntile * BN + row0) * CDIM + kq * 4;
    const float* bptr1 = Wo + (size_t)(ntile * BN + row1) * CDIM + kq * 4;

    const int ty = tid >> 4;
    const int tx = tid & 15;

    float acc[8][8];
#pragma unroll
    for (int r = 0; r < 8; r++)
#pragma unroll
        for (int c = 0; c < 8; c++) acc[r][c] = 0.f;

    for (int k0 = 0; k0 < CDIM; k0 += BK) {
        float4 a0 = *(const float4*)(aptr0 + k0);
        float4 a1 = *(const float4*)(aptr1 + k0);
        float4 b0 = *(const float4*)(bptr0 + k0);
        float4 b1 = *(const float4*)(bptr1 + k0);
        const int kc = kq * 4;
        As[kc + 0][row0] = a0.x; As[kc + 1][row0] = a0.y;
        As[kc + 2][row0] = a0.z; As[kc + 3][row0] = a0.w;
        As[kc + 0][row1] = a1.x; As[kc + 1][row1] = a1.y;
        As[kc + 2][row1] = a1.z; As[kc + 3][row1] = a1.w;
        Bs[kc + 0][row0] = b0.x; Bs[kc + 1][row0] = b0.y;
        Bs[kc + 2][row0] = b0.z; Bs[kc + 3][row0] = b0.w;
        Bs[kc + 0][row1] = b1.x; Bs[kc + 1][row1] = b1.y;
        Bs[kc + 2][row1] = b1.z; Bs[kc + 3][row1] = b1.w;
        __syncthreads();

#pragma unroll
        for (int k = 0; k < BK; k++) {
            float a[8], b[8];
            *(float4*)(a)     = *(const float4*)&As[k][ty * 8];
            *(float4*)(a + 4) = *(const float4*)&As[k][ty * 8 + 4];
            *(float4*)(b)     = *(const float4*)&Bs[k][tx * 8];
            *(float4*)(b + 4) = *(const float4*)&Bs[k][tx * 8 + 4];
#pragma unroll
            for (int r = 0; r < 8; r++)
#pragma unroll
                for (int c = 0; c < 8; c++) acc[r][c] += a[r] * b[c];
        }
        __syncthreads();
    }

    // bias for this thread's 8 output columns
    float bias[8];
#pragma unroll
    for (int c = 0; c < 8; c++) bias[c] = bo[ntile * BN + tx * 8 + c];

#pragma unroll
    for (int r = 0; r < 8; r++) {
        const int m = mtile * BM + ty * 8 + r;
        const int n = win_to_src(m);
        float* op = y + (size_t)n * CDIM + ntile * BN + tx * 8;
        *(float4*)(op)     = make_float4(acc[r][0] + bias[0], acc[r][1] + bias[1],
                                         acc[r][2] + bias[2], acc[r][3] + bias[3]);
        *(float4*)(op + 4) = make_float4(acc[r][4] + bias[4], acc[r][5] + bias[5],
                                         acc[r][6] + bias[6], acc[r][7] + bias[7]);
    }
}

// =====================================================================
// Kernel 2: per-(window, head) attention.
// S = Q K^T * 0.125 ; softmax rows ; O = P V
// grid: NWIN*NHEAD = 4096 ; 256 threads ; ~166 KB dynamic smem
// =====================================================================
#define QS_LD 132                // [64][132]
#define VS_LD 68                 // [128][68]
#define SS_LD 132                // [128][132]
#define QS_OFF 0
#define KS_OFF (64 * QS_LD)
#define VS_OFF (KS_OFF + 64 * QS_LD)
#define SS_OFF (VS_OFF + 128 * VS_LD)
#define ATTN_SMEM_FLOATS (SS_OFF + 128 * SS_LD)
#define ATTN_SMEM_BYTES (ATTN_SMEM_FLOATS * 4)

__global__ __launch_bounds__(256, 1)
void attn_kernel()
{
    extern __shared__ float sm[];
    float* Qs = sm + QS_OFF;   // Qs[d][l]
    float* Ks = sm + KS_OFF;   // Ks[d][l]
    float* Vs = sm + VS_OFF;   // Vs[l][d]
    float* Ss = sm + SS_OFF;   // Ss[i][j]

    const int tid = threadIdx.x;
    const int w = blockIdx.x >> 3;
    const int h = blockIdx.x & 7;

    const float* qb = g_q + (size_t)(w * LWIN) * CDIM + h * HDIM;
    const float* kb = g_k + (size_t)(w * LWIN) * CDIM + h * HDIM;
    const float* vb = g_v + (size_t)(w * LWIN) * CDIM + h * HDIM;

    // ---- stage Q,K (d-major) and V (l-major) into smem ----
#pragma unroll
    for (int it = 0; it < 8; it++) {
        int i = tid + it * 256;          // 0..2047 float4 slots
        int li = i >> 4;                 // token in window, 0..127
        int dq = i & 15;                 // float4 index within 64 dims
        size_t go = (size_t)li * CDIM + dq * 4;
        float4 qv = *(const float4*)(qb + go);
        float4 kv = *(const float4*)(kb + go);
        float4 vv = *(const float4*)(vb + go);
        int d = dq * 4;
        Qs[(d + 0) * QS_LD + li] = qv.x; Qs[(d + 1) * QS_LD + li] = qv.y;
        Qs[(d + 2) * QS_LD + li] = qv.z; Qs[(d + 3) * QS_LD + li] = qv.w;
        Ks[(d + 0) * QS_LD + li] = kv.x; Ks[(d + 1) * QS_LD + li] = kv.y;
        Ks[(d + 2) * QS_LD + li] = kv.z; Ks[(d + 3) * QS_LD + li] = kv.w;
        *(float4*)&Vs[li * VS_LD + d] = vv;
    }
    __syncthreads();

    // ---- S = Q K^T * scale (8x8 micro-tiles) ----
    {
        const int ty = tid >> 4, tx = tid & 15;
        float acc[8][8];
#pragma unroll
        for (int r = 0; r < 8; r++)
#pragma unroll
            for (int c = 0; c < 8; c++) acc[r][c] = 0.f;

#pragma unroll 4
        for (int d = 0; d < HDIM; d++) {
            float a[8], b[8];
            *(float4*)(a)     = *(const float4*)&Qs[d * QS_LD + ty * 8];
            *(float4*)(a + 4) = *(const float4*)&Qs[d * QS_LD + ty * 8 + 4];
            *(float4*)(b)     = *(const float4*)&Ks[d * QS_LD + tx * 8];
            *(float4*)(b + 4) = *(const float4*)&Ks[d * QS_LD + tx * 8 + 4];
#pragma unroll
            for (int r = 0; r < 8; r++)
#pragma unroll
                for (int c = 0; c < 8; c++) acc[r][c] += a[r] * b[c];
        }
        const float scale = 0.125f;   // 1/sqrt(64)
#pragma unroll
        for (int r = 0; r < 8; r++) {
            float* sp = &Ss[(ty * 8 + r) * SS_LD + tx * 8];
            *(float4*)(sp)     = make_float4(acc[r][0] * scale, acc[r][1] * scale,
                                             acc[r][2] * scale, acc[r][3] * scale);
            *(float4*)(sp + 4) = make_float4(acc[r][4] * scale, acc[r][5] * scale,
                                             acc[r][6] * scale, acc[r][7] * scale);
        }
    }
    __syncthreads();

    // ---- row softmax (one thread per row) ----
    if (tid < LWIN) {
        float* row = &Ss[tid * SS_LD];
        float mx = row[0];
#pragma unroll 8
        for (int j = 1; j < LWIN; j++) mx = fmaxf(mx, row[j]);
        float s = 0.f;
#pragma unroll 8
        for (int j = 0; j < LWIN; j++) {
            float e = __expf(row[j] - mx);
            row[j] = e;
            s += e;
        }
        float inv = 1.f / s;
#pragma unroll 8
        for (int j = 0; j < LWIN; j++) row[j] *= inv;
    }
    __syncthreads();

    // ---- O = P V (8x4 micro-tiles) ----
    {
        const int ty = tid >> 4, tx = tid & 15;
        float oacc[8][4];
#pragma unroll
        for (int r = 0; r < 8; r++)
#pragma unroll
            for (int c = 0; c < 4; c++) oacc[r][c] = 0.f;

#pragma unroll 4
        for (int l = 0; l < LWIN; l++) {
            float4 bv = *(const float4*)&Vs[l * VS_LD + tx * 4];
#pragma unroll
            for (int r = 0; r < 8; r++) {
                float a = Ss[(ty * 8 + r) * SS_LD + l];
                oacc[r][0] += a * bv.x;
                oacc[r][1] += a * bv.y;
                oacc[r][2] += a * bv.z;
                oacc[r][3] += a * bv.w;
            }
        }
#pragma unroll
        for (int r = 0; r < 8; r++) {
            float* op = g_o + (size_t)(w * LWIN + ty * 8 + r) * CDIM + h * HDIM + tx * 4;
            *(float4*)op = make_float4(oacc[r][0], oacc[r][1], oacc[r][2], oacc[r][3]);
        }
    }
}

// =====================================================================
// launcher
// =====================================================================
extern "C" void kernel_launch(void* const* d_in, const int* in_sizes, int n_in,
                              void* d_out, int out_size)
{
    (void)in_sizes; (void)n_in; (void)out_size;
    const float* x  = (const float*)d_in[0];
    const float* Wq = (const float*)d_in[1];
    const float* Wk = (const float*)d_in[2];
    const float* Wv = (const float*)d_in[3];
    const float* Wo = (const float*)d_in[4];
    const float* bo = (const float*)d_in[5];
    float* y = (float*)d_out;

    cudaFuncSetAttribute(attn_kernel, cudaFuncAttributeMaxDynamicSharedMemorySize,
                         ATTN_SMEM_BYTES);

    qkv_gemm<<<dim3(12, 512), 256>>>(x, Wq, Wk, Wv);
    attn_kernel<<<NWIN * NHEAD, 256, ATTN_SMEM_BYTES>>>();
    proj_gemm<<<dim3(4, 512), 256>>>(Wo, bo, y);
}

// round 4
// speedup vs baseline: 2.4468x; 2.4468x over previous
#include <cuda_runtime.h>
#include <cuda_bf16.h>
#include <cuda_fp16.h>
#include <cstdint>
#include <math.h>

// ---------------- problem constants ----------------
#define NTOK   65536
#define CDIM   512
#define NWIN   512
#define LWIN   128
#define NHEAD  8
#define HDIM   64
#define K3     1536          // 3 * CDIM (split-bf16 K expansion)

// ---------------- scratch ----------------
__device__ __half g_q16[(size_t)NTOK * CDIM];
__device__ __half g_k16[(size_t)NTOK * CDIM];
__device__ __half g_v16[(size_t)NTOK * CDIM];
__device__ __nv_bfloat16 g_a3[(size_t)NTOK * K3];        // A3 for qkv; reused by attn output for proj
__device__ __nv_bfloat16 g_w3[(size_t)4 * CDIM * K3];    // Wq,Wk,Wv,Wo split

// windowed row m -> natural token index n
__device__ __forceinline__ int win_to_src(int m) {
    int w = m >> 7, l = m & 127;
    int w1 = w & 7, h1 = (w >> 3) & 7, f1 = w >> 6;
    int iw = l & 7, ih = (l >> 3) & 7, t  = l >> 6;
    return ((f1 * 2 + t) << 12) + ((h1 * 8 + ih) << 6) + (w1 * 8 + iw);
}

// ---------------- PTX helpers (arch-neutral: sm_80+) ----------------
__device__ __forceinline__ uint32_t smem_u32(const void* p) {
    uint32_t a;
    asm("{ .reg .u64 t; cvta.to.shared.u64 t, %1; cvt.u32.u64 %0, t; }" : "=r"(a) : "l"(p));
    return a;
}
#define CP16(dst, src) \
    asm volatile("cp.async.cg.shared.global [%0], [%1], 16;" :: "r"(dst), "l"(src))
#define CP_COMMIT() asm volatile("cp.async.commit_group;" ::: "memory")
#define CP_WAIT1()  asm volatile("cp.async.wait_group 1;" ::: "memory")
#define CP_WAIT0()  asm volatile("cp.async.wait_group 0;" ::: "memory")

#define LDSM4(r0, r1, r2, r3, a) \
    asm volatile("ldmatrix.sync.aligned.m8n8.x4.shared.b16 {%0,%1,%2,%3}, [%4];" \
                 : "=r"(r0), "=r"(r1), "=r"(r2), "=r"(r3) : "r"(a))
#define LDSM2(r0, r1, a) \
    asm volatile("ldmatrix.sync.aligned.m8n8.x2.shared.b16 {%0,%1}, [%2];" \
                 : "=r"(r0), "=r"(r1) : "r"(a))
#define LDSM2T(r0, r1, a) \
    asm volatile("ldmatrix.sync.aligned.m8n8.x2.trans.shared.b16 {%0,%1}, [%2];" \
                 : "=r"(r0), "=r"(r1) : "r"(a))

#define MMA_BF16(c, a, b) \
    asm volatile("mma.sync.aligned.m16n8k16.row.col.f32.bf16.bf16.f32 " \
                 "{%0,%1,%2,%3}, {%4,%5,%6,%7}, {%8,%9}, {%0,%1,%2,%3};" \
                 : "+f"((c)[0]), "+f"((c)[1]), "+f"((c)[2]), "+f"((c)[3]) \
                 : "r"((a)[0]), "r"((a)[1]), "r"((a)[2]), "r"((a)[3]), \
                   "r"((b)[0]), "r"((b)[1]))
#define MMA_F16(c, a, b) \
    asm volatile("mma.sync.aligned.m16n8k16.row.col.f32.f16.f16.f32 " \
                 "{%0,%1,%2,%3}, {%4,%5,%6,%7}, {%8,%9}, {%0,%1,%2,%3};" \
                 : "+f"((c)[0]), "+f"((c)[1]), "+f"((c)[2]), "+f"((c)[3]) \
                 : "r"((a)[0]), "r"((a)[1]), "r"((a)[2]), "r"((a)[3]), \
                   "r"((b)[0]), "r"((b)[1]))

// ---------------- split-bf16 packing ----------------
__device__ __forceinline__ uint32_t pk(__nv_bfloat16 a, __nv_bfloat16 b) {
    __nv_bfloat162 t; t.x = a; t.y = b;
    return *reinterpret_cast<uint32_t*>(&t);
}
__device__ __forceinline__ void split_pack4(float4 v, uint2& hi, uint2& lo) {
    __nv_bfloat16 hx = __float2bfloat16_rn(v.x), hy = __float2bfloat16_rn(v.y);
    __nv_bfloat16 hz = __float2bfloat16_rn(v.z), hw = __float2bfloat16_rn(v.w);
    __nv_bfloat16 lx = __float2bfloat16_rn(v.x - __bfloat162float(hx));
    __nv_bfloat16 ly = __float2bfloat16_rn(v.y - __bfloat162float(hy));
    __nv_bfloat16 lz = __float2bfloat16_rn(v.z - __bfloat162float(hz));
    __nv_bfloat16 lw = __float2bfloat16_rn(v.w - __bfloat162float(hw));
    hi.x = pk(hx, hy); hi.y = pk(hz, hw);
    lo.x = pk(lx, ly); lo.y = pk(lz, lw);
}
__device__ __forceinline__ void split_pack2(float a, float b, uint32_t& hi, uint32_t& lo) {
    __nv_bfloat16 ha = __float2bfloat16_rn(a), hb = __float2bfloat16_rn(b);
    __nv_bfloat16 la = __float2bfloat16_rn(a - __bfloat162float(ha));
    __nv_bfloat16 lb = __float2bfloat16_rn(b - __bfloat162float(hb));
    hi = pk(ha, hb); lo = pk(la, lb);
}

// =====================================================================
// conversion kernels
// =====================================================================
__global__ void convert_x(const float* __restrict__ x) {
    int idx = blockIdx.x * 256 + threadIdx.x;
    int m = idx >> 7, q = idx & 127;
    int n = win_to_src(m);
    float4 v = *(const float4*)(x + (size_t)n * CDIM + q * 4);
    uint2 hi, lo; split_pack4(v, hi, lo);
    __nv_bfloat16* base = g_a3 + (size_t)m * K3 + q * 4;
    *(uint2*)(base)        = hi;
    *(uint2*)(base + 512)  = lo;
    *(uint2*)(base + 1024) = hi;
}

__global__ void convert_w(const float* __restrict__ Wq, const float* __restrict__ Wk,
                          const float* __restrict__ Wv, const float* __restrict__ Wo) {
    int sel = blockIdx.x >> 8;
    int rem = (blockIdx.x & 255) * 256 + threadIdx.x;
    int m = rem >> 7, q = rem & 127;
    const float* W = (sel == 0) ? Wq : (sel == 1) ? Wk : (sel == 2) ? Wv : Wo;
    float4 v = *(const float4*)(W + (size_t)m * CDIM + q * 4);
    uint2 hi, lo; split_pack4(v, hi, lo);
    __nv_bfloat16* base = g_w3 + (size_t)sel * CDIM * K3 + (size_t)m * K3 + q * 4;
    *(uint2*)(base)        = hi;
    *(uint2*)(base + 512)  = hi;
    *(uint2*)(base + 1024) = lo;
}

// =====================================================================
// mma.sync GEMM: C[128,128] = A3[128,K3] @ B3[128,K3]^T, bf16 in, f32 acc.
// 256 threads = 8 warps (2m x 4n), warp tile 64x32. BK=64, double buffered.
// smem row stride: 72 bf16 = 144B (36 words === 4 mod 32 -> conflict-free).
// =====================================================================
#define GSTRIDE   144                     // bytes per smem row
#define GTILE_B   (128 * GSTRIDE)         // 18432 per matrix per stage
#define GSTAGE_B  (2 * GTILE_B)           // 36864 per stage (A+B)
#define GEMM_SMEM_BYTES (2 * GSTAGE_B)    // 73728
#define NCHUNK    (K3 / 64)               // 24

__device__ __forceinline__ void gemm_prefetch(const __nv_bfloat16* __restrict__ A,
                                              const __nv_bfloat16* __restrict__ B,
                                              uint32_t sa, uint32_t sb, int c) {
    const int tid = threadIdx.x;
#pragma unroll
    for (int i = 0; i < 4; i++) {
        int idx = tid + i * 256;
        int row = idx >> 3, c8 = idx & 7;
        uint32_t so = row * GSTRIDE + c8 * 16;
        CP16(sa + so, A + (size_t)row * K3 + c * 64 + c8 * 8);
        CP16(sb + so, B + (size_t)row * K3 + c * 64 + c8 * 8);
    }
    CP_COMMIT();
}

__device__ __forceinline__ void gemm_mainloop(const __nv_bfloat16* __restrict__ A,
                                              const __nv_bfloat16* __restrict__ B,
                                              uint32_t smem, float acc[4][4][4]) {
    const int tid  = threadIdx.x;
    const int wid  = tid >> 5;
    const int lane = tid & 31;
    const int wm   = wid >> 2;      // 0..1
    const int wn   = wid & 3;       // 0..3

    // A frag addresses (x4): lanes 0-15 -> rows 0-15 @k0 ; lanes 16-31 -> rows 0-15 @k8
    const uint32_t aLane = (uint32_t)(wm * 64 + (lane & 15)) * GSTRIDE + (lane >> 4) * 16;
    // B frag addresses (x2): lanes 0-7 -> n-rows @k0 ; lanes 8-15 -> SAME n-rows @k8
    const uint32_t bLane = (uint32_t)(wn * 32 + (lane & 7)) * GSTRIDE
                         + ((lane >> 3) & 1) * 16;

#pragma unroll
    for (int mf = 0; mf < 4; mf++)
#pragma unroll
        for (int nf = 0; nf < 4; nf++)
#pragma unroll
            for (int r = 0; r < 4; r++) acc[mf][nf][r] = 0.f;

    gemm_prefetch(A, B, smem, smem + GTILE_B, 0);
    gemm_prefetch(A, B, smem + GSTAGE_B, smem + GSTAGE_B + GTILE_B, 1);

    for (int c = 0; c < NCHUNK; c++) {
        CP_WAIT1();
        __syncthreads();
        const uint32_t sa = smem + (c & 1) * GSTAGE_B;
        const uint32_t sb = sa + GTILE_B;
#pragma unroll
        for (int ks = 0; ks < 4; ks++) {
            uint32_t a[4][4], b[4][2];
#pragma unroll
            for (int mf = 0; mf < 4; mf++)
                LDSM4(a[mf][0], a[mf][1], a[mf][2], a[mf][3],
                      sa + aLane + mf * (16 * GSTRIDE) + ks * 32);
#pragma unroll
            for (int nf = 0; nf < 4; nf++)
                LDSM2(b[nf][0], b[nf][1],
                      sb + bLane + nf * (8 * GSTRIDE) + ks * 32);
#pragma unroll
            for (int mf = 0; mf < 4; mf++)
#pragma unroll
                for (int nf = 0; nf < 4; nf++)
                    MMA_BF16(acc[mf][nf], a[mf], b[nf]);
        }
        __syncthreads();
        if (c + 2 < NCHUNK) {
            const uint32_t pa = smem + (c & 1) * GSTAGE_B;
            gemm_prefetch(A, B, pa, pa + GTILE_B, c + 2);
        } else {
            CP_COMMIT();   // keep group count in lockstep
        }
    }
    CP_WAIT0();
}

// qkv: grid (12, 512); bx = wsel*4 + ntile. Writes fp16 (Q scaled by 0.125).
__global__ __launch_bounds__(256, 2)
void qkv_mma() {
    extern __shared__ char smc[];
    uint32_t smem = smem_u32(smc);
    const int wsel  = blockIdx.x >> 2;
    const int ntile = blockIdx.x & 3;
    const int m0    = blockIdx.y * 128;

    const __nv_bfloat16* A = g_a3 + (size_t)m0 * K3;
    const __nv_bfloat16* B = g_w3 + (size_t)wsel * CDIM * K3 + (size_t)(ntile * 128) * K3;

    float acc[4][4][4];
    gemm_mainloop(A, B, smem, acc);

    __half* Out = (wsel == 0) ? g_q16 : (wsel == 1) ? g_k16 : g_v16;
    const float mul = (wsel == 0) ? 0.125f : 1.0f;

    const int tid = threadIdx.x, wid = tid >> 5, lane = tid & 31;
    const int wm = wid >> 2, wn = wid & 3;
    const int g = lane >> 2, tg = lane & 3;
#pragma unroll
    for (int mf = 0; mf < 4; mf++) {
        const int r0 = m0 + wm * 64 + mf * 16 + g;
#pragma unroll
        for (int nf = 0; nf < 4; nf++) {
            const int col = ntile * 128 + wn * 32 + nf * 8 + 2 * tg;
            __half2 h0 = __float22half2_rn(make_float2(acc[mf][nf][0] * mul, acc[mf][nf][1] * mul));
            __half2 h1 = __float22half2_rn(make_float2(acc[mf][nf][2] * mul, acc[mf][nf][3] * mul));
            *(__half2*)(Out + (size_t)r0 * CDIM + col)       = h0;
            *(__half2*)(Out + (size_t)(r0 + 8) * CDIM + col) = h1;
        }
    }
}

// proj: grid (4, 512). A = g_a3 (attn output split), bias + window-merge scatter.
__global__ __launch_bounds__(256, 2)
void proj_mma(const float* __restrict__ bo, float* __restrict__ y) {
    extern __shared__ char smc[];
    uint32_t smem = smem_u32(smc);
    const int ntile = blockIdx.x;
    const int m0    = blockIdx.y * 128;

    const __nv_bfloat16* A = g_a3 + (size_t)m0 * K3;
    const __nv_bfloat16* B = g_w3 + (size_t)3 * CDIM * K3 + (size_t)(ntile * 128) * K3;

    float acc[4][4][4];
    gemm_mainloop(A, B, smem, acc);

    const int tid = threadIdx.x, wid = tid >> 5, lane = tid & 31;
    const int wm = wid >> 2, wn = wid & 3;
    const int g = lane >> 2, tg = lane & 3;
#pragma unroll
    for (int mf = 0; mf < 4; mf++) {
        const int r0 = m0 + wm * 64 + mf * 16 + g;
        const int n0 = win_to_src(r0);
        const int n1 = win_to_src(r0 + 8);
#pragma unroll
        for (int nf = 0; nf < 4; nf++) {
            const int col = ntile * 128 + wn * 32 + nf * 8 + 2 * tg;
            const float b0 = bo[col], b1 = bo[col + 1];
            *(float2*)(y + (size_t)n0 * CDIM + col) =
                make_float2(acc[mf][nf][0] + b0, acc[mf][nf][1] + b1);
            *(float2*)(y + (size_t)n1 * CDIM + col) =
                make_float2(acc[mf][nf][2] + b0, acc[mf][nf][3] + b1);
        }
    }
}

// =====================================================================
// attention: fp16 mma.sync per (window, head). 256 threads, 4096 blocks.
// S = (Q*0.125) K^T (K=64) ; softmax ; O = P V (K=128).
// Epilogue writes split-bf16 straight into g_a3 for proj.
// =====================================================================
#define ASTRIDE 144                      // Qs/Ks/Vs row stride bytes (72 halves)
#define SSTRIDE 272                      // Ss row stride bytes (136 halves)
#define QS_OFF  0
#define KS_OFF  (128 * ASTRIDE)          // 18432
#define VS_OFF  (2 * 128 * ASTRIDE)      // 36864
#define SS_OFF  (3 * 128 * ASTRIDE)      // 55296
#define ATTN_SMEM_BYTES (SS_OFF + 128 * SSTRIDE)   // 90112

__global__ __launch_bounds__(256, 2)
void attn_mma() {
    extern __shared__ char smc[];
    uint32_t smem = smem_u32(smc);
    const int tid  = threadIdx.x;
    const int wid  = tid >> 5;
    const int lane = tid & 31;
    const int w = blockIdx.x >> 3;
    const int h = blockIdx.x & 7;

    // ---- load Q,K,V fp16 tiles [128][64] ----
    const size_t base = (size_t)(w * LWIN) * CDIM + h * HDIM;
#pragma unroll
    for (int i = 0; i < 4; i++) {
        int idx = tid + i * 256;
        int row = idx >> 3, c8 = idx & 7;
        size_t go = base + (size_t)row * CDIM + c8 * 8;
        uint32_t so = row * ASTRIDE + c8 * 16;
        *(uint4*)(smc + QS_OFF + so) = *(const uint4*)(g_q16 + go);
        *(uint4*)(smc + KS_OFF + so) = *(const uint4*)(g_k16 + go);
        *(uint4*)(smc + VS_OFF + so) = *(const uint4*)(g_v16 + go);
    }
    __syncthreads();

    // ---- S = Q K^T : warps 2m x 4n, warp tile 64x32, K=64 ----
    {
        const int wm = wid >> 2, wn = wid & 3;
        const uint32_t aLane = smem + QS_OFF
            + (uint32_t)(wm * 64 + (lane & 15)) * ASTRIDE + (lane >> 4) * 16;
        const uint32_t bLane = smem + KS_OFF
            + (uint32_t)(wn * 32 + (lane & 7)) * ASTRIDE
            + ((lane >> 3) & 1) * 16;

        float acc[4][4][4];
#pragma unroll
        for (int mf = 0; mf < 4; mf++)
#pragma unroll
            for (int nf = 0; nf < 4; nf++)
#pragma unroll
                for (int r = 0; r < 4; r++) acc[mf][nf][r] = 0.f;

#pragma unroll
        for (int ks = 0; ks < 4; ks++) {
            uint32_t a[4][4], b[4][2];
#pragma unroll
            for (int mf = 0; mf < 4; mf++)
                LDSM4(a[mf][0], a[mf][1], a[mf][2], a[mf][3],
                      aLane + mf * (16 * ASTRIDE) + ks * 32);
#pragma unroll
            for (int nf = 0; nf < 4; nf++)
                LDSM2(b[nf][0], b[nf][1], bLane + nf * (8 * ASTRIDE) + ks * 32);
#pragma unroll
            for (int mf = 0; mf < 4; mf++)
#pragma unroll
                for (int nf = 0; nf < 4; nf++)
                    MMA_F16(acc[mf][nf], a[mf], b[nf]);
        }

        const int g = lane >> 2, tg = lane & 3;
#pragma unroll
        for (int mf = 0; mf < 4; mf++) {
            const int r0 = wm * 64 + mf * 16 + g;
#pragma unroll
            for (int nf = 0; nf < 4; nf++) {
                const int col = wn * 32 + nf * 8 + 2 * tg;
                *(__half2*)(smc + SS_OFF + r0 * SSTRIDE + col * 2) =
                    __float22half2_rn(make_float2(acc[mf][nf][0], acc[mf][nf][1]));
                *(__half2*)(smc + SS_OFF + (r0 + 8) * SSTRIDE + col * 2) =
                    __float22half2_rn(make_float2(acc[mf][nf][2], acc[mf][nf][3]));
            }
        }
    }
    __syncthreads();

    // ---- softmax: one thread per row, fp16 in/out, fp32 math ----
    if (tid < LWIN) {
        __half2* row = (__half2*)(smc + SS_OFF + tid * SSTRIDE);
        float mx = -1e30f;
#pragma unroll 8
        for (int j = 0; j < 64; j++) {
            float2 f = __half22float2(row[j]);
            mx = fmaxf(mx, fmaxf(f.x, f.y));
        }
        float s = 0.f;
#pragma unroll 8
        for (int j = 0; j < 64; j++) {
            float2 f = __half22float2(row[j]);
            f.x = __expf(f.x - mx); f.y = __expf(f.y - mx);
            s += f.x + f.y;
            row[j] = __float22half2_rn(f);
        }
        float inv = 1.f / s;
#pragma unroll 8
        for (int j = 0; j < 64; j++) {
            float2 f = __half22float2(row[j]);
            row[j] = __float22half2_rn(make_float2(f.x * inv, f.y * inv));
        }
    }
    __syncthreads();

    // ---- O = P V : warps 4m x 2n, warp tile 32x32, K=128 ----
    {
        const int wm = wid >> 1, wn = wid & 1;
        const uint32_t aLane = smem + SS_OFF
            + (uint32_t)(wm * 32 + (lane & 15)) * SSTRIDE + (lane >> 4) * 16;
        const uint32_t bLane = smem + VS_OFF
            + (uint32_t)((lane & 7) + ((lane >> 3) & 1) * 8) * ASTRIDE
            + (wn * 32) * 2;

        float acc[2][4][4];
#pragma unroll
        for (int mf = 0; mf < 2; mf++)
#pragma unroll
            for (int nf = 0; nf < 4; nf++)
#pragma unroll
                for (int r = 0; r < 4; r++) acc[mf][nf][r] = 0.f;

#pragma unroll
        for (int ks = 0; ks < 8; ks++) {
            uint32_t a[2][4], b[4][2];
#pragma unroll
            for (int mf = 0; mf < 2; mf++)
                LDSM4(a[mf][0], a[mf][1], a[mf][2], a[mf][3],
                      aLane + mf * (16 * SSTRIDE) + ks * 32);
#pragma unroll
            for (int nf = 0; nf < 4; nf++)
                LDSM2T(b[nf][0], b[nf][1],
                       bLane + ks * (16 * ASTRIDE) + nf * 16);
#pragma unroll
            for (int mf = 0; mf < 2; mf++)
#pragma unroll
                for (int nf = 0; nf < 4; nf++)
                    MMA_F16(acc[mf][nf], a[mf], b[nf]);
        }

        const int g = lane >> 2, tg = lane & 3;
#pragma unroll
        for (int mf = 0; mf < 2; mf++) {
            const int m = w * LWIN + wm * 32 + mf * 16 + g;
#pragma unroll
            for (int nf = 0; nf < 4; nf++) {
                const int col = h * HDIM + wn * 32 + nf * 8 + 2 * tg;
                uint32_t hi, lo;
                split_pack2(acc[mf][nf][0], acc[mf][nf][1], hi, lo);
                __nv_bfloat16* d0 = g_a3 + (size_t)m * K3 + col;
                *(uint32_t*)(d0)        = hi;
                *(uint32_t*)(d0 + 512)  = lo;
                *(uint32_t*)(d0 + 1024) = hi;
                split_pack2(acc[mf][nf][2], acc[mf][nf][3], hi, lo);
                __nv_bfloat16* d1 = g_a3 + (size_t)(m + 8) * K3 + col;
                *(uint32_t*)(d1)        = hi;
                *(uint32_t*)(d1 + 512)  = lo;
                *(uint32_t*)(d1 + 1024) = hi;
            }
        }
    }
}

// =====================================================================
// launcher
// =====================================================================
extern "C" void kernel_launch(void* const* d_in, const int* in_sizes, int n_in,
                              void* d_out, int out_size)
{
    (void)in_sizes; (void)n_in; (void)out_size;
    const float* x  = (const float*)d_in[0];
    const float* Wq = (const float*)d_in[1];
    const float* Wk = (const float*)d_in[2];
    const float* Wv = (const float*)d_in[3];
    const float* Wo = (const float*)d_in[4];
    const float* bo = (const float*)d_in[5];
    float* y = (float*)d_out;

    cudaFuncSetAttribute(qkv_mma,  cudaFuncAttributeMaxDynamicSharedMemorySize, GEMM_SMEM_BYTES);
    cudaFuncSetAttribute(proj_mma, cudaFuncAttributeMaxDynamicSharedMemorySize, GEMM_SMEM_BYTES);
    cudaFuncSetAttribute(attn_mma, cudaFuncAttributeMaxDynamicSharedMemorySize, ATTN_SMEM_BYTES);

    convert_w<<<1024, 256>>>(Wq, Wk, Wv, Wo);
    convert_x<<<32768, 256>>>(x);
    qkv_mma<<<dim3(12, 512), 256, GEMM_SMEM_BYTES>>>();
    attn_mma<<<NWIN * NHEAD, 256, ATTN_SMEM_BYTES>>>();
    proj_mma<<<dim3(4, 512), 256, GEMM_SMEM_BYTES>>>(bo, y);
}

// round 5
// speedup vs baseline: 5.7240x; 2.3393x over previous
#include <cuda_runtime.h>
#include <cuda_fp16.h>
#include <cstdint>
#include <math.h>

// ---------------- problem constants ----------------
#define NTOK   65536
#define CDIM   512
#define NWIN   512
#define LWIN   128
#define NHEAD  8
#define HDIM   64

// ---------------- scratch ----------------
__device__ __half g_x16[(size_t)NTOK * CDIM];   // windowed x, fp16
__device__ __half g_q16[(size_t)NTOK * CDIM];
__device__ __half g_k16[(size_t)NTOK * CDIM];
__device__ __half g_v16[(size_t)NTOK * CDIM];
__device__ __half g_ao[(size_t)NTOK * CDIM];    // attention output (windowed rows)
__device__ __half g_w16[(size_t)4 * CDIM * CDIM]; // Wq,Wk,Wv,Wo fp16

// windowed row m -> natural token index n
__device__ __forceinline__ int win_to_src(int m) {
    int w = m >> 7, l = m & 127;
    int w1 = w & 7, h1 = (w >> 3) & 7, f1 = w >> 6;
    int iw = l & 7, ih = (l >> 3) & 7, t  = l >> 6;
    return ((f1 * 2 + t) << 12) + ((h1 * 8 + ih) << 6) + (w1 * 8 + iw);
}

// ---------------- PTX helpers (arch-neutral: sm_80+) ----------------
__device__ __forceinline__ uint32_t smem_u32(const void* p) {
    uint32_t a;
    asm("{ .reg .u64 t; cvta.to.shared.u64 t, %1; cvt.u32.u64 %0, t; }" : "=r"(a) : "l"(p));
    return a;
}
#define CP16(dst, src) \
    asm volatile("cp.async.cg.shared.global [%0], [%1], 16;" :: "r"(dst), "l"(src))
#define CP_COMMIT() asm volatile("cp.async.commit_group;" ::: "memory")
#define CP_WAIT1()  asm volatile("cp.async.wait_group 1;" ::: "memory")
#define CP_WAIT0()  asm volatile("cp.async.wait_group 0;" ::: "memory")

#define LDSM4(r0, r1, r2, r3, a) \
    asm volatile("ldmatrix.sync.aligned.m8n8.x4.shared.b16 {%0,%1,%2,%3}, [%4];" \
                 : "=r"(r0), "=r"(r1), "=r"(r2), "=r"(r3) : "r"(a))
#define LDSM2(r0, r1, a) \
    asm volatile("ldmatrix.sync.aligned.m8n8.x2.shared.b16 {%0,%1}, [%2];" \
                 : "=r"(r0), "=r"(r1) : "r"(a))
#define LDSM2T(r0, r1, a) \
    asm volatile("ldmatrix.sync.aligned.m8n8.x2.trans.shared.b16 {%0,%1}, [%2];" \
                 : "=r"(r0), "=r"(r1) : "r"(a))

#define MMA_F16(c, a, b) \
    asm volatile("mma.sync.aligned.m16n8k16.row.col.f32.f16.f16.f32 " \
                 "{%0,%1,%2,%3}, {%4,%5,%6,%7}, {%8,%9}, {%0,%1,%2,%3};" \
                 : "+f"((c)[0]), "+f"((c)[1]), "+f"((c)[2]), "+f"((c)[3]) \
                 : "r"((a)[0]), "r"((a)[1]), "r"((a)[2]), "r"((a)[3]), \
                   "r"((b)[0]), "r"((b)[1]))

// =====================================================================
// conversion kernels
// =====================================================================
__global__ void convert_x(const float* __restrict__ x) {
    int idx = blockIdx.x * 256 + threadIdx.x;     // NTOK*128 threads
    int m = idx >> 7, q = idx & 127;
    int n = win_to_src(m);
    float4 v = *(const float4*)(x + (size_t)n * CDIM + q * 4);
    __half2 h0 = __float22half2_rn(make_float2(v.x, v.y));
    __half2 h1 = __float22half2_rn(make_float2(v.z, v.w));
    __half* dst = g_x16 + (size_t)m * CDIM + q * 4;
    *(__half2*)(dst)     = h0;
    *(__half2*)(dst + 2) = h1;
}

__global__ void convert_w(const float* __restrict__ Wq, const float* __restrict__ Wk,
                          const float* __restrict__ Wv, const float* __restrict__ Wo) {
    int sel = blockIdx.x >> 8;                    // 256 blocks per matrix
    int rem = (blockIdx.x & 255) * 256 + threadIdx.x;
    const float* W = (sel == 0) ? Wq : (sel == 1) ? Wk : (sel == 2) ? Wv : Wo;
    float4 v = *(const float4*)(W + (size_t)rem * 4);
    __half2 h0 = __float22half2_rn(make_float2(v.x, v.y));
    __half2 h1 = __float22half2_rn(make_float2(v.z, v.w));
    __half* dst = g_w16 + (size_t)sel * CDIM * CDIM + (size_t)rem * 4;
    *(__half2*)(dst)     = h0;
    *(__half2*)(dst + 2) = h1;
}

// =====================================================================
// mma.sync GEMM: C[128,128] = A[128,512] @ B[128,512]^T, fp16 in, f32 acc.
// 256 threads = 8 warps (2m x 4n), warp tile 64x32. BK=64, double buffered.
// smem row stride 144B (72 halves): 36 words === 4 mod 32 -> conflict-free.
// =====================================================================
#define GSTRIDE   144
#define GTILE_B   (128 * GSTRIDE)         // 18432
#define GSTAGE_B  (2 * GTILE_B)           // 36864
#define GEMM_SMEM_BYTES (2 * GSTAGE_B)    // 73728
#define NCHUNK    (CDIM / 64)             // 8

__device__ __forceinline__ void gemm_prefetch(const __half* __restrict__ A,
                                              const __half* __restrict__ B,
                                              uint32_t sa, uint32_t sb, int c) {
    const int tid = threadIdx.x;
#pragma unroll
    for (int i = 0; i < 4; i++) {
        int idx = tid + i * 256;
        int row = idx >> 3, c8 = idx & 7;
        uint32_t so = row * GSTRIDE + c8 * 16;
        CP16(sa + so, A + (size_t)row * CDIM + c * 64 + c8 * 8);
        CP16(sb + so, B + (size_t)row * CDIM + c * 64 + c8 * 8);
    }
    CP_COMMIT();
}

__device__ __forceinline__ void gemm_mainloop(const __half* __restrict__ A,
                                              const __half* __restrict__ B,
                                              uint32_t smem, float acc[4][4][4]) {
    const int tid  = threadIdx.x;
    const int wid  = tid >> 5;
    const int lane = tid & 31;
    const int wm   = wid >> 2;      // 0..1
    const int wn   = wid & 3;       // 0..3

    // A frag (x4): lanes 0-15 -> rows @k0 ; lanes 16-31 -> same rows @k8
    const uint32_t aLane = (uint32_t)(wm * 64 + (lane & 15)) * GSTRIDE + (lane >> 4) * 16;
    // B frag (x2): lanes 0-7 -> n-rows @k0 ; lanes 8-15 -> SAME n-rows @k8
    const uint32_t bLane = (uint32_t)(wn * 32 + (lane & 7)) * GSTRIDE
                         + ((lane >> 3) & 1) * 16;

#pragma unroll
    for (int mf = 0; mf < 4; mf++)
#pragma unroll
        for (int nf = 0; nf < 4; nf++)
#pragma unroll
            for (int r = 0; r < 4; r++) acc[mf][nf][r] = 0.f;

    gemm_prefetch(A, B, smem, smem + GTILE_B, 0);
    gemm_prefetch(A, B, smem + GSTAGE_B, smem + GSTAGE_B + GTILE_B, 1);

    for (int c = 0; c < NCHUNK; c++) {
        CP_WAIT1();
        __syncthreads();
        const uint32_t sa = smem + (c & 1) * GSTAGE_B;
        const uint32_t sb = sa + GTILE_B;
#pragma unroll
        for (int ks = 0; ks < 4; ks++) {
            uint32_t a[4][4], b[4][2];
#pragma unroll
            for (int mf = 0; mf < 4; mf++)
                LDSM4(a[mf][0], a[mf][1], a[mf][2], a[mf][3],
                      sa + aLane + mf * (16 * GSTRIDE) + ks * 32);
#pragma unroll
            for (int nf = 0; nf < 4; nf++)
                LDSM2(b[nf][0], b[nf][1],
                      sb + bLane + nf * (8 * GSTRIDE) + ks * 32);
#pragma unroll
            for (int mf = 0; mf < 4; mf++)
#pragma unroll
                for (int nf = 0; nf < 4; nf++)
                    MMA_F16(acc[mf][nf], a[mf], b[nf]);
        }
        __syncthreads();
        if (c + 2 < NCHUNK) {
            const uint32_t pa = smem + (c & 1) * GSTAGE_B;
            gemm_prefetch(A, B, pa, pa + GTILE_B, c + 2);
        } else {
            CP_COMMIT();
        }
    }
    CP_WAIT0();
}

// qkv: grid (12, 512); bx = wsel*4 + ntile. Writes fp16 (Q scaled by 0.125).
__global__ __launch_bounds__(256, 2)
void qkv_mma() {
    extern __shared__ char smc[];
    uint32_t smem = smem_u32(smc);
    const int wsel  = blockIdx.x >> 2;
    const int ntile = blockIdx.x & 3;
    const int m0    = blockIdx.y * 128;

    const __half* A = g_x16 + (size_t)m0 * CDIM;
    const __half* B = g_w16 + (size_t)wsel * CDIM * CDIM + (size_t)(ntile * 128) * CDIM;

    float acc[4][4][4];
    gemm_mainloop(A, B, smem, acc);

    __half* Out = (wsel == 0) ? g_q16 : (wsel == 1) ? g_k16 : g_v16;
    const float mul = (wsel == 0) ? 0.125f : 1.0f;

    const int tid = threadIdx.x, wid = tid >> 5, lane = tid & 31;
    const int wm = wid >> 2, wn = wid & 3;
    const int g = lane >> 2, tg = lane & 3;
#pragma unroll
    for (int mf = 0; mf < 4; mf++) {
        const int r0 = m0 + wm * 64 + mf * 16 + g;
#pragma unroll
        for (int nf = 0; nf < 4; nf++) {
            const int col = ntile * 128 + wn * 32 + nf * 8 + 2 * tg;
            __half2 h0 = __float22half2_rn(make_float2(acc[mf][nf][0] * mul, acc[mf][nf][1] * mul));
            __half2 h1 = __float22half2_rn(make_float2(acc[mf][nf][2] * mul, acc[mf][nf][3] * mul));
            *(__half2*)(Out + (size_t)r0 * CDIM + col)       = h0;
            *(__half2*)(Out + (size_t)(r0 + 8) * CDIM + col) = h1;
        }
    }
}

// proj: grid (4, 512). A = g_ao, bias + window-merge scatter to fp32 y.
__global__ __launch_bounds__(256, 2)
void proj_mma(const float* __restrict__ bo, float* __restrict__ y) {
    extern __shared__ char smc[];
    uint32_t smem = smem_u32(smc);
    const int ntile = blockIdx.x;
    const int m0    = blockIdx.y * 128;

    const __half* A = g_ao + (size_t)m0 * CDIM;
    const __half* B = g_w16 + (size_t)3 * CDIM * CDIM + (size_t)(ntile * 128) * CDIM;

    float acc[4][4][4];
    gemm_mainloop(A, B, smem, acc);

    const int tid = threadIdx.x, wid = tid >> 5, lane = tid & 31;
    const int wm = wid >> 2, wn = wid & 3;
    const int g = lane >> 2, tg = lane & 3;
#pragma unroll
    for (int mf = 0; mf < 4; mf++) {
        const int r0 = m0 + wm * 64 + mf * 16 + g;
        const int n0 = win_to_src(r0);
        const int n1 = win_to_src(r0 + 8);
#pragma unroll
        for (int nf = 0; nf < 4; nf++) {
            const int col = ntile * 128 + wn * 32 + nf * 8 + 2 * tg;
            const float b0 = bo[col], b1 = bo[col + 1];
            *(float2*)(y + (size_t)n0 * CDIM + col) =
                make_float2(acc[mf][nf][0] + b0, acc[mf][nf][1] + b1);
            *(float2*)(y + (size_t)n1 * CDIM + col) =
                make_float2(acc[mf][nf][2] + b0, acc[mf][nf][3] + b1);
        }
    }
}

// =====================================================================
// attention: fp16 mma.sync per (window, head). 256 threads, 4096 blocks.
// S = (Q*0.125) K^T (K=64) ; softmax (2 threads/row) ; O = P V (K=128).
// =====================================================================
#define ASTRIDE 144                      // Qs/Ks/Vs row stride bytes (72 halves)
#define SSTRIDE 272                      // Ss row stride bytes (136 halves)
#define QS_OFF  0
#define KS_OFF  (128 * ASTRIDE)          // 18432
#define VS_OFF  (2 * 128 * ASTRIDE)      // 36864
#define SS_OFF  (3 * 128 * ASTRIDE)      // 55296
#define ATTN_SMEM_BYTES (SS_OFF + 128 * SSTRIDE)   // 90112

__global__ __launch_bounds__(256, 2)
void attn_mma() {
    extern __shared__ char smc[];
    uint32_t smem = smem_u32(smc);
    const int tid  = threadIdx.x;
    const int wid  = tid >> 5;
    const int lane = tid & 31;
    const int w = blockIdx.x >> 3;
    const int h = blockIdx.x & 7;

    // ---- load Q,K,V fp16 tiles [128][64] ----
    const size_t base = (size_t)(w * LWIN) * CDIM + h * HDIM;
#pragma unroll
    for (int i = 0; i < 4; i++) {
        int idx = tid + i * 256;
        int row = idx >> 3, c8 = idx & 7;
        size_t go = base + (size_t)row * CDIM + c8 * 8;
        uint32_t so = row * ASTRIDE + c8 * 16;
        *(uint4*)(smc + QS_OFF + so) = *(const uint4*)(g_q16 + go);
        *(uint4*)(smc + KS_OFF + so) = *(const uint4*)(g_k16 + go);
        *(uint4*)(smc + VS_OFF + so) = *(const uint4*)(g_v16 + go);
    }
    __syncthreads();

    // ---- S = Q K^T : warps 2m x 4n, warp tile 64x32, K=64 ----
    {
        const int wm = wid >> 2, wn = wid & 3;
        const uint32_t aLane = smem + QS_OFF
            + (uint32_t)(wm * 64 + (lane & 15)) * ASTRIDE + (lane >> 4) * 16;
        const uint32_t bLane = smem + KS_OFF
            + (uint32_t)(wn * 32 + (lane & 7)) * ASTRIDE
            + ((lane >> 3) & 1) * 16;

        float acc[4][4][4];
#pragma unroll
        for (int mf = 0; mf < 4; mf++)
#pragma unroll
            for (int nf = 0; nf < 4; nf++)
#pragma unroll
                for (int r = 0; r < 4; r++) acc[mf][nf][r] = 0.f;

#pragma unroll
        for (int ks = 0; ks < 4; ks++) {
            uint32_t a[4][4], b[4][2];
#pragma unroll
            for (int mf = 0; mf < 4; mf++)
                LDSM4(a[mf][0], a[mf][1], a[mf][2], a[mf][3],
                      aLane + mf * (16 * ASTRIDE) + ks * 32);
#pragma unroll
            for (int nf = 0; nf < 4; nf++)
                LDSM2(b[nf][0], b[nf][1], bLane + nf * (8 * ASTRIDE) + ks * 32);
#pragma unroll
            for (int mf = 0; mf < 4; mf++)
#pragma unroll
                for (int nf = 0; nf < 4; nf++)
                    MMA_F16(acc[mf][nf], a[mf], b[nf]);
        }

        const int g = lane >> 2, tg = lane & 3;
#pragma unroll
        for (int mf = 0; mf < 4; mf++) {
            const int r0 = wm * 64 + mf * 16 + g;
#pragma unroll
            for (int nf = 0; nf < 4; nf++) {
                const int col = wn * 32 + nf * 8 + 2 * tg;
                *(__half2*)(smc + SS_OFF + r0 * SSTRIDE + col * 2) =
                    __float22half2_rn(make_float2(acc[mf][nf][0], acc[mf][nf][1]));
                *(__half2*)(smc + SS_OFF + (r0 + 8) * SSTRIDE + col * 2) =
                    __float22half2_rn(make_float2(acc[mf][nf][2], acc[mf][nf][3]));
            }
        }
    }
    __syncthreads();

    // ---- softmax: 2 threads per row (shfl.xor combine), fp32 math ----
    {
        const int row = tid >> 1;
        const int half = tid & 1;
        __half2* rp = (__half2*)(smc + SS_OFF + row * SSTRIDE) + half * 32;

        float mx0 = -1e30f, mx1 = -1e30f;
#pragma unroll 8
        for (int j = 0; j < 32; j += 2) {
            float2 f0 = __half22float2(rp[j]);
            float2 f1 = __half22float2(rp[j + 1]);
            mx0 = fmaxf(mx0, fmaxf(f0.x, f0.y));
            mx1 = fmaxf(mx1, fmaxf(f1.x, f1.y));
        }
        float mx = fmaxf(mx0, mx1);
        mx = fmaxf(mx, __shfl_xor_sync(0xffffffff, mx, 1));

        float s0 = 0.f, s1 = 0.f;
#pragma unroll 8
        for (int j = 0; j < 32; j += 2) {
            float2 f0 = __half22float2(rp[j]);
            float2 f1 = __half22float2(rp[j + 1]);
            f0.x = __expf(f0.x - mx); f0.y = __expf(f0.y - mx);
            f1.x = __expf(f1.x - mx); f1.y = __expf(f1.y - mx);
            s0 += f0.x + f0.y; s1 += f1.x + f1.y;
            rp[j]     = __float22half2_rn(f0);
            rp[j + 1] = __float22half2_rn(f1);
        }
        float s = s0 + s1;
        s += __shfl_xor_sync(0xffffffff, s, 1);
        float inv = 1.f / s;
#pragma unroll 8
        for (int j = 0; j < 32; j++) {
            float2 f = __half22float2(rp[j]);
            rp[j] = __float22half2_rn(make_float2(f.x * inv, f.y * inv));
        }
    }
    __syncthreads();

    // ---- O = P V : warps 4m x 2n, warp tile 32x32, K=128 ----
    {
        const int wm = wid >> 1, wn = wid & 1;
        const uint32_t aLane = smem + SS_OFF
            + (uint32_t)(wm * 32 + (lane & 15)) * SSTRIDE + (lane >> 4) * 16;
        const uint32_t bLane = smem + VS_OFF
            + (uint32_t)((lane & 7) + ((lane >> 3) & 1) * 8) * ASTRIDE
            + (wn * 32) * 2;

        float acc[2][4][4];
#pragma unroll
        for (int mf = 0; mf < 2; mf++)
#pragma unroll
            for (int nf = 0; nf < 4; nf++)
#pragma unroll
                for (int r = 0; r < 4; r++) acc[mf][nf][r] = 0.f;

#pragma unroll
        for (int ks = 0; ks < 8; ks++) {
            uint32_t a[2][4], b[4][2];
#pragma unroll
            for (int mf = 0; mf < 2; mf++)
                LDSM4(a[mf][0], a[mf][1], a[mf][2], a[mf][3],
                      aLane + mf * (16 * SSTRIDE) + ks * 32);
#pragma unroll
            for (int nf = 0; nf < 4; nf++)
                LDSM2T(b[nf][0], b[nf][1],
                       bLane + ks * (16 * ASTRIDE) + nf * 16);
#pragma unroll
            for (int mf = 0; mf < 2; mf++)
#pragma unroll
                for (int nf = 0; nf < 4; nf++)
                    MMA_F16(acc[mf][nf], a[mf], b[nf]);
        }

        const int g = lane >> 2, tg = lane & 3;
#pragma unroll
        for (int mf = 0; mf < 2; mf++) {
            const int m = w * LWIN + wm * 32 + mf * 16 + g;
#pragma unroll
            for (int nf = 0; nf < 4; nf++) {
                const int col = h * HDIM + wn * 32 + nf * 8 + 2 * tg;
                *(__half2*)(g_ao + (size_t)m * CDIM + col) =
                    __float22half2_rn(make_float2(acc[mf][nf][0], acc[mf][nf][1]));
                *(__half2*)(g_ao + (size_t)(m + 8) * CDIM + col) =
                    __float22half2_rn(make_float2(acc[mf][nf][2], acc[mf][nf][3]));
            }
        }
    }
}

// =====================================================================
// launcher
// =====================================================================
extern "C" void kernel_launch(void* const* d_in, const int* in_sizes, int n_in,
                              void* d_out, int out_size)
{
    (void)in_sizes; (void)n_in; (void)out_size;
    const float* x  = (const float*)d_in[0];
    const float* Wq = (const float*)d_in[1];
    const float* Wk = (const float*)d_in[2];
    const float* Wv = (const float*)d_in[3];
    const float* Wo = (const float*)d_in[4];
    const float* bo = (const float*)d_in[5];
    float* y = (float*)d_out;

    cudaFuncSetAttribute(qkv_mma,  cudaFuncAttributeMaxDynamicSharedMemorySize, GEMM_SMEM_BYTES);
    cudaFuncSetAttribute(proj_mma, cudaFuncAttributeMaxDynamicSharedMemorySize, GEMM_SMEM_BYTES);
    cudaFuncSetAttribute(attn_mma, cudaFuncAttributeMaxDynamicSharedMemorySize, ATTN_SMEM_BYTES);

    convert_w<<<1024, 256>>>(Wq, Wk, Wv, Wo);
    convert_x<<<32768, 256>>>(x);
    qkv_mma<<<dim3(12, 512), 256, GEMM_SMEM_BYTES>>>();
    attn_mma<<<NWIN * NHEAD, 256, ATTN_SMEM_BYTES>>>();
    proj_mma<<<dim3(4, 512), 256, GEMM_SMEM_BYTES>>>(bo, y);
}

// round 6
// speedup vs baseline: 6.3506x; 1.1095x over previous
#include <cuda_runtime.h>
#include <cuda_fp16.h>
#include <cstdint>
#include <math.h>

// ---------------- problem constants ----------------
#define NTOK   65536
#define CDIM   512
#define NWIN   512
#define LWIN   128
#define NHEAD  8
#define HDIM   64

// ---------------- scratch ----------------
__device__ __half g_x16[(size_t)NTOK * CDIM];   // windowed x, fp16
__device__ __half g_q16[(size_t)NTOK * CDIM];   // Q pre-scaled by 0.125
__device__ __half g_k16[(size_t)NTOK * CDIM];
__device__ __half g_v16[(size_t)NTOK * CDIM];
__device__ __half g_ao[(size_t)NTOK * CDIM];    // attention output (windowed rows)
__device__ __half g_w16[(size_t)4 * CDIM * CDIM];

// windowed row m -> natural token index n
__device__ __forceinline__ int win_to_src(int m) {
    int w = m >> 7, l = m & 127;
    int w1 = w & 7, h1 = (w >> 3) & 7, f1 = w >> 6;
    int iw = l & 7, ih = (l >> 3) & 7, t  = l >> 6;
    return ((f1 * 2 + t) << 12) + ((h1 * 8 + ih) << 6) + (w1 * 8 + iw);
}

// ---------------- PTX helpers ----------------
__device__ __forceinline__ uint32_t smem_u32(const void* p) {
    uint32_t a;
    asm("{ .reg .u64 t; cvta.to.shared.u64 t, %1; cvt.u32.u64 %0, t; }" : "=r"(a) : "l"(p));
    return a;
}
#define CP16(dst, src) \
    asm volatile("cp.async.cg.shared.global [%0], [%1], 16;" :: "r"(dst), "l"(src))
#define CP_COMMIT() asm volatile("cp.async.commit_group;" ::: "memory")
#define CP_WAIT1()  asm volatile("cp.async.wait_group 1;" ::: "memory")
#define CP_WAIT0()  asm volatile("cp.async.wait_group 0;" ::: "memory")

#define LDSM4(r0, r1, r2, r3, a) \
    asm volatile("ldmatrix.sync.aligned.m8n8.x4.shared.b16 {%0,%1,%2,%3}, [%4];" \
                 : "=r"(r0), "=r"(r1), "=r"(r2), "=r"(r3) : "r"(a))
#define LDSM2(r0, r1, a) \
    asm volatile("ldmatrix.sync.aligned.m8n8.x2.shared.b16 {%0,%1}, [%2];" \
                 : "=r"(r0), "=r"(r1) : "r"(a))
#define LDSM4T(r0, r1, r2, r3, a) \
    asm volatile("ldmatrix.sync.aligned.m8n8.x4.trans.shared.b16 {%0,%1,%2,%3}, [%4];" \
                 : "=r"(r0), "=r"(r1), "=r"(r2), "=r"(r3) : "r"(a))

#define MMA_F16(c, a, b) \
    asm volatile("mma.sync.aligned.m16n8k16.row.col.f32.f16.f16.f32 " \
                 "{%0,%1,%2,%3}, {%4,%5,%6,%7}, {%8,%9}, {%0,%1,%2,%3};" \
                 : "+f"((c)[0]), "+f"((c)[1]), "+f"((c)[2]), "+f"((c)[3]) \
                 : "r"((a)[0]), "r"((a)[1]), "r"((a)[2]), "r"((a)[3]), \
                   "r"((b)[0]), "r"((b)[1]))

__device__ __forceinline__ uint32_t pkh(float a, float b) {
    __half2 h = __float22half2_rn(make_float2(a, b));
    return *reinterpret_cast<uint32_t*>(&h);
}

// =====================================================================
// conversion kernels
// =====================================================================
__global__ void convert_x(const float* __restrict__ x) {
    int idx = blockIdx.x * 256 + threadIdx.x;
    int m = idx >> 7, q = idx & 127;
    int n = win_to_src(m);
    float4 v = *(const float4*)(x + (size_t)n * CDIM + q * 4);
    __half* dst = g_x16 + (size_t)m * CDIM + q * 4;
    *(__half2*)(dst)     = __float22half2_rn(make_float2(v.x, v.y));
    *(__half2*)(dst + 2) = __float22half2_rn(make_float2(v.z, v.w));
}

__global__ void convert_w(const float* __restrict__ Wq, const float* __restrict__ Wk,
                          const float* __restrict__ Wv, const float* __restrict__ Wo) {
    int sel = blockIdx.x >> 8;
    int rem = (blockIdx.x & 255) * 256 + threadIdx.x;
    const float* W = (sel == 0) ? Wq : (sel == 1) ? Wk : (sel == 2) ? Wv : Wo;
    float4 v = *(const float4*)(W + (size_t)rem * 4);
    __half* dst = g_w16 + (size_t)sel * CDIM * CDIM + (size_t)rem * 4;
    *(__half2*)(dst)     = __float22half2_rn(make_float2(v.x, v.y));
    *(__half2*)(dst + 2) = __float22half2_rn(make_float2(v.z, v.w));
}

// =====================================================================
// mma.sync GEMM: C[128,128] = A[128,512] @ B[128,512]^T, 3-stage cp.async.
// 256 threads = 8 warps (2m x 4n), warp tile 64x32. BK=64.
// =====================================================================
#define GSTRIDE   144
#define GTILE_B   (128 * GSTRIDE)         // 18432
#define GSTAGE_B  (2 * GTILE_B)           // 36864
#define GEMM_SMEM_BYTES (3 * GSTAGE_B)    // 110592
#define NCHUNK    (CDIM / 64)             // 8

__device__ __forceinline__ void gemm_prefetch(const __half* __restrict__ A,
                                              const __half* __restrict__ B,
                                              uint32_t sa, uint32_t sb, int c) {
    const int tid = threadIdx.x;
#pragma unroll
    for (int i = 0; i < 4; i++) {
        int idx = tid + i * 256;
        int row = idx >> 3, c8 = idx & 7;
        uint32_t so = row * GSTRIDE + c8 * 16;
        CP16(sa + so, A + (size_t)row * CDIM + c * 64 + c8 * 8);
        CP16(sb + so, B + (size_t)row * CDIM + c * 64 + c8 * 8);
    }
    CP_COMMIT();
}

__device__ __forceinline__ void gemm_mainloop(const __half* __restrict__ A,
                                              const __half* __restrict__ B,
                                              uint32_t smem, float acc[4][4][4]) {
    const int tid  = threadIdx.x;
    const int wid  = tid >> 5;
    const int lane = tid & 31;
    const int wm   = wid >> 2;
    const int wn   = wid & 3;

    const uint32_t aLane = (uint32_t)(wm * 64 + (lane & 15)) * GSTRIDE + (lane >> 4) * 16;
    const uint32_t bLane = (uint32_t)(wn * 32 + (lane & 7)) * GSTRIDE
                         + ((lane >> 3) & 1) * 16;

#pragma unroll
    for (int mf = 0; mf < 4; mf++)
#pragma unroll
        for (int nf = 0; nf < 4; nf++)
#pragma unroll
            for (int r = 0; r < 4; r++) acc[mf][nf][r] = 0.f;

    gemm_prefetch(A, B, smem, smem + GTILE_B, 0);
    gemm_prefetch(A, B, smem + GSTAGE_B, smem + GSTAGE_B + GTILE_B, 1);

    for (int c = 0; c < NCHUNK; c++) {
        CP_WAIT1();
        __syncthreads();                    // one barrier per chunk
        if (c + 2 < NCHUNK) {
            const uint32_t pb = smem + ((c + 2) % 3) * GSTAGE_B;  // buffer freed last iter
            gemm_prefetch(A, B, pb, pb + GTILE_B, c + 2);
        } else {
            CP_COMMIT();                    // keep group counting aligned
        }
        const uint32_t sa = smem + (c % 3) * GSTAGE_B;
        const uint32_t sb = sa + GTILE_B;
#pragma unroll
        for (int ks = 0; ks < 4; ks++) {
            uint32_t a[4][4], b[4][2];
#pragma unroll
            for (int mf = 0; mf < 4; mf++)
                LDSM4(a[mf][0], a[mf][1], a[mf][2], a[mf][3],
                      sa + aLane + mf * (16 * GSTRIDE) + ks * 32);
#pragma unroll
            for (int nf = 0; nf < 4; nf++)
                LDSM2(b[nf][0], b[nf][1],
                      sb + bLane + nf * (8 * GSTRIDE) + ks * 32);
#pragma unroll
            for (int mf = 0; mf < 4; mf++)
#pragma unroll
                for (int nf = 0; nf < 4; nf++)
                    MMA_F16(acc[mf][nf], a[mf], b[nf]);
        }
    }
    CP_WAIT0();
}

// qkv: grid (12, 512); bx = wsel*4 + ntile. Writes fp16 (Q scaled by 0.125).
__global__ __launch_bounds__(256, 2)
void qkv_mma() {
    extern __shared__ char smc[];
    uint32_t smem = smem_u32(smc);
    const int wsel  = blockIdx.x >> 2;
    const int ntile = blockIdx.x & 3;
    const int m0    = blockIdx.y * 128;

    const __half* A = g_x16 + (size_t)m0 * CDIM;
    const __half* B = g_w16 + (size_t)wsel * CDIM * CDIM + (size_t)(ntile * 128) * CDIM;

    float acc[4][4][4];
    gemm_mainloop(A, B, smem, acc);

    __half* Out = (wsel == 0) ? g_q16 : (wsel == 1) ? g_k16 : g_v16;
    const float mul = (wsel == 0) ? 0.125f : 1.0f;

    const int tid = threadIdx.x, wid = tid >> 5, lane = tid & 31;
    const int wm = wid >> 2, wn = wid & 3;
    const int g = lane >> 2, tg = lane & 3;
#pragma unroll
    for (int mf = 0; mf < 4; mf++) {
        const int r0 = m0 + wm * 64 + mf * 16 + g;
#pragma unroll
        for (int nf = 0; nf < 4; nf++) {
            const int col = ntile * 128 + wn * 32 + nf * 8 + 2 * tg;
            *(uint32_t*)(Out + (size_t)r0 * CDIM + col) =
                pkh(acc[mf][nf][0] * mul, acc[mf][nf][1] * mul);
            *(uint32_t*)(Out + (size_t)(r0 + 8) * CDIM + col) =
                pkh(acc[mf][nf][2] * mul, acc[mf][nf][3] * mul);
        }
    }
}

// proj: grid (4, 512). A = g_ao, bias + window-merge scatter to fp32 y.
__global__ __launch_bounds__(256, 2)
void proj_mma(const float* __restrict__ bo, float* __restrict__ y) {
    extern __shared__ char smc[];
    uint32_t smem = smem_u32(smc);
    const int ntile = blockIdx.x;
    const int m0    = blockIdx.y * 128;

    const __half* A = g_ao + (size_t)m0 * CDIM;
    const __half* B = g_w16 + (size_t)3 * CDIM * CDIM + (size_t)(ntile * 128) * CDIM;

    float acc[4][4][4];
    gemm_mainloop(A, B, smem, acc);

    const int tid = threadIdx.x, wid = tid >> 5, lane = tid & 31;
    const int wm = wid >> 2, wn = wid & 3;
    const int g = lane >> 2, tg = lane & 3;
#pragma unroll
    for (int mf = 0; mf < 4; mf++) {
        const int r0 = m0 + wm * 64 + mf * 16 + g;
        const int n0 = win_to_src(r0);
        const int n1 = win_to_src(r0 + 8);
#pragma unroll
        for (int nf = 0; nf < 4; nf++) {
            const int col = ntile * 128 + wn * 32 + nf * 8 + 2 * tg;
            const float b0 = bo[col], b1 = bo[col + 1];
            *(float2*)(y + (size_t)n0 * CDIM + col) =
                make_float2(acc[mf][nf][0] + b0, acc[mf][nf][1] + b1);
            *(float2*)(y + (size_t)n1 * CDIM + col) =
                make_float2(acc[mf][nf][2] + b0, acc[mf][nf][3] + b1);
        }
    }
}

// =====================================================================
// attention v2: warp-owns-rows. 8 warps x 16 rows. S in fp32 registers,
// softmax via quad shuffles, P stays in registers as A-fragments for PV.
// grid 4096 (window*8 + head), 256 threads.
// =====================================================================
#define ASTRIDE 144
#define QS_OFF  0
#define KS_OFF  (128 * ASTRIDE)          // 18432
#define VS_OFF  (2 * 128 * ASTRIDE)      // 36864
#define ATTN_SMEM_BYTES (3 * 128 * ASTRIDE)   // 55296

__global__ __launch_bounds__(256, 2)
void attn_mma() {
    extern __shared__ char smc[];
    uint32_t smem = smem_u32(smc);
    const int tid  = threadIdx.x;
    const int wid  = tid >> 5;
    const int lane = tid & 31;
    const int win = blockIdx.x >> 3;
    const int h   = blockIdx.x & 7;

    // ---- load Q,K,V fp16 tiles [128][64] into smem ----
    const size_t base = (size_t)(win * LWIN) * CDIM + h * HDIM;
#pragma unroll
    for (int i = 0; i < 4; i++) {
        int idx = tid + i * 256;
        int row = idx >> 3, c8 = idx & 7;
        size_t go = base + (size_t)row * CDIM + c8 * 8;
        uint32_t so = row * ASTRIDE + c8 * 16;
        *(uint4*)(smc + QS_OFF + so) = *(const uint4*)(g_q16 + go);
        *(uint4*)(smc + KS_OFF + so) = *(const uint4*)(g_k16 + go);
        *(uint4*)(smc + VS_OFF + so) = *(const uint4*)(g_v16 + go);
    }
    __syncthreads();

    // ---- S = Q K^T : warp tile 16x128 (warp wid -> rows 16*wid..+15) ----
    float s[16][4];
#pragma unroll
    for (int nf = 0; nf < 16; nf++)
#pragma unroll
        for (int r = 0; r < 4; r++) s[nf][r] = 0.f;

    const uint32_t aLane = smem + QS_OFF
        + (uint32_t)(wid * 16 + (lane & 15)) * ASTRIDE + (lane >> 4) * 16;
    const uint32_t bBase = smem + KS_OFF
        + (uint32_t)((lane & 7) + ((lane >> 4) & 1) * 8) * ASTRIDE
        + ((lane >> 3) & 1) * 16;

#pragma unroll
    for (int ks = 0; ks < 4; ks++) {
        uint32_t a[4];
        LDSM4(a[0], a[1], a[2], a[3], aLane + ks * 32);
#pragma unroll
        for (int nfp = 0; nfp < 8; nfp++) {
            uint32_t b[4];
            LDSM4(b[0], b[1], b[2], b[3], bBase + nfp * (16 * ASTRIDE) + ks * 32);
            MMA_F16(s[2 * nfp],     a, b);
            MMA_F16(s[2 * nfp + 1], a, b + 2);
        }
    }

    // ---- softmax in registers (rows r0 = 16*wid + g, r1 = r0 + 8) ----
    float mx0 = -1e30f, mx1 = -1e30f;
#pragma unroll
    for (int nf = 0; nf < 16; nf++) {
        mx0 = fmaxf(mx0, fmaxf(s[nf][0], s[nf][1]));
        mx1 = fmaxf(mx1, fmaxf(s[nf][2], s[nf][3]));
    }
    mx0 = fmaxf(mx0, __shfl_xor_sync(0xffffffff, mx0, 1));
    mx0 = fmaxf(mx0, __shfl_xor_sync(0xffffffff, mx0, 2));
    mx1 = fmaxf(mx1, __shfl_xor_sync(0xffffffff, mx1, 1));
    mx1 = fmaxf(mx1, __shfl_xor_sync(0xffffffff, mx1, 2));

    float s0 = 0.f, s1 = 0.f;
#pragma unroll
    for (int nf = 0; nf < 16; nf++) {
        s[nf][0] = __expf(s[nf][0] - mx0);
        s[nf][1] = __expf(s[nf][1] - mx0);
        s[nf][2] = __expf(s[nf][2] - mx1);
        s[nf][3] = __expf(s[nf][3] - mx1);
        s0 += s[nf][0] + s[nf][1];
        s1 += s[nf][2] + s[nf][3];
    }
    s0 += __shfl_xor_sync(0xffffffff, s0, 1);
    s0 += __shfl_xor_sync(0xffffffff, s0, 2);
    s1 += __shfl_xor_sync(0xffffffff, s1, 1);
    s1 += __shfl_xor_sync(0xffffffff, s1, 2);
    const float inv0 = 1.f / s0, inv1 = 1.f / s1;

    // pack P into A-fragments for m16n8k16 (k-block j covers cols 16j..16j+15)
    uint32_t aP[8][4];
#pragma unroll
    for (int j = 0; j < 8; j++) {
        aP[j][0] = pkh(s[2 * j][0]     * inv0, s[2 * j][1]     * inv0);
        aP[j][1] = pkh(s[2 * j][2]     * inv1, s[2 * j][3]     * inv1);
        aP[j][2] = pkh(s[2 * j + 1][0] * inv0, s[2 * j + 1][1] * inv0);
        aP[j][3] = pkh(s[2 * j + 1][2] * inv1, s[2 * j + 1][3] * inv1);
    }

    // ---- O = P V : warp rows 16*wid..+15, all 64 cols ----
    float o[8][4];
#pragma unroll
    for (int nf = 0; nf < 8; nf++)
#pragma unroll
        for (int r = 0; r < 4; r++) o[nf][r] = 0.f;

    const uint32_t vBase = smem + VS_OFF
        + (uint32_t)((lane & 7) + ((lane >> 3) & 1) * 8) * ASTRIDE
        + ((lane >> 4) & 1) * 16;

#pragma unroll
    for (int j = 0; j < 8; j++) {
#pragma unroll
        for (int nfp = 0; nfp < 4; nfp++) {
            uint32_t b[4];
            LDSM4T(b[0], b[1], b[2], b[3], vBase + j * (16 * ASTRIDE) + nfp * 32);
            MMA_F16(o[2 * nfp],     aP[j], b);
            MMA_F16(o[2 * nfp + 1], aP[j], b + 2);
        }
    }

    // ---- store O (fp16, windowed rows) ----
    const int g = lane >> 2, tg = lane & 3;
    const int m0 = win * LWIN + wid * 16;
#pragma unroll
    for (int nf = 0; nf < 8; nf++) {
        const int col = h * HDIM + nf * 8 + 2 * tg;
        *(uint32_t*)(g_ao + (size_t)(m0 + g) * CDIM + col)     = pkh(o[nf][0], o[nf][1]);
        *(uint32_t*)(g_ao + (size_t)(m0 + g + 8) * CDIM + col) = pkh(o[nf][2], o[nf][3]);
    }
}

// =====================================================================
// launcher
// =====================================================================
extern "C" void kernel_launch(void* const* d_in, const int* in_sizes, int n_in,
                              void* d_out, int out_size)
{
    (void)in_sizes; (void)n_in; (void)out_size;
    const float* x  = (const float*)d_in[0];
    const float* Wq = (const float*)d_in[1];
    const float* Wk = (const float*)d_in[2];
    const float* Wv = (const float*)d_in[3];
    const float* Wo = (const float*)d_in[4];
    const float* bo = (const float*)d_in[5];
    float* y = (float*)d_out;

    cudaFuncSetAttribute(qkv_mma,  cudaFuncAttributeMaxDynamicSharedMemorySize, GEMM_SMEM_BYTES);
    cudaFuncSetAttribute(proj_mma, cudaFuncAttributeMaxDynamicSharedMemorySize, GEMM_SMEM_BYTES);
    cudaFuncSetAttribute(attn_mma, cudaFuncAttributeMaxDynamicSharedMemorySize, ATTN_SMEM_BYTES);

    convert_w<<<1024, 256>>>(Wq, Wk, Wv, Wo);
    convert_x<<<32768, 256>>>(x);
    qkv_mma<<<dim3(12, 512), 256, GEMM_SMEM_BYTES>>>();
    attn_mma<<<NWIN * NHEAD, 256, ATTN_SMEM_BYTES>>>();
    proj_mma<<<dim3(4, 512), 256, GEMM_SMEM_BYTES>>>(bo, y);
}